// round 16
// baseline (speedup 1.0000x reference)
#include <cuda_runtime.h>
#include <cstdint>

// Problem constants
#define NN   32
#define CC   512
#define HWL  3136        // 56*56
#define GG   8
#define LL   64
#define MTOT 100352      // NN*HWL
#define EPSV 1e-4f
#define NPART 128        // 32 n-chunks * 4 k-chunks
#define RL   68          // smem row stride (floats) for cov's [ch][k]
#define PRX  136         // apply: paired-row stride in floats (64 (hi,lo) + 8 pad)

// ---------------- scratch (device globals; no allocation allowed) -------------
__device__ float g_pcov[GG][NPART][LL * LL];  // partial F = HH^T + H(2L)^T
__device__ float g_psum[GG][NPART][LL];       // partial channel sums
__device__ float g_mu[CC];
__device__ float g_cov[GG * LL * LL];
__device__ float g_subT[GG * LL * LL];        // whitening subspace, TRANSPOSED [g][k][i] = S[i][k]
__device__ float g_t[CC];                     // t[c] = sum_j S[c][j] * mu[g*64+j]

// ---------------- helpers ------------------------------------------------------
__device__ __forceinline__ void mma_tf32(float c[4],
                                         uint32_t a0, uint32_t a1, uint32_t a2, uint32_t a3,
                                         uint32_t b0, uint32_t b1) {
    asm volatile(
        "mma.sync.aligned.m16n8k8.row.col.f32.tf32.tf32.f32 "
        "{%0,%1,%2,%3}, {%4,%5,%6,%7}, {%8,%9}, {%0,%1,%2,%3};"
        : "+f"(c[0]), "+f"(c[1]), "+f"(c[2]), "+f"(c[3])
        : "r"(a0), "r"(a1), "r"(a2), "r"(a3), "r"(b0), "r"(b1));
}
__device__ __forceinline__ float hi_tf32(float x) {
    return __uint_as_float(__float_as_uint(x) & 0xFFFFE000u);
}
__device__ __forceinline__ uint32_t fbits(float x) { return __float_as_uint(x); }

// =============================================================================
// Kernel 1: partial F = H H^T + H (2L)^T via tf32 MMA (R15 verbatim).
// grid (4 k-chunks, 32 n, 8 g), 256 threads (8 warps).
// =============================================================================
__global__ __launch_bounds__(256) void k_cov_partial(const float* __restrict__ x) {
    const int q = blockIdx.x;           // k-chunk 0..3
    const int n = blockIdx.y;
    const int g = blockIdx.z;
    __shared__ __align__(16) float Xhi[64 * RL];
    __shared__ __align__(16) float Xlo[64 * RL];   // holds 2*lo

    const int tid = threadIdx.x, wid = tid >> 5, lane = tid & 31;
    const int r = lane >> 2, c = lane & 3;
    const int mbase = (wid & 3) * 16;
    const int nt0   = (wid >> 2) * 4;
    const int lr = tid >> 4, lc = tid & 15;

    const int tiles = (q == 0) ? 13 : 12;
    const int k0    = (q == 0) ? 0 : (832 + (q - 1) * 768);
    const float* base = x + ((size_t)n * CC + (size_t)g * LL) * HWL + k0;

    float acc[4][4];
    #pragma unroll
    for (int t = 0; t < 4; ++t)
        #pragma unroll
        for (int j = 0; j < 4; ++j) acc[t][j] = 0.f;
    float psum[4] = {0.f, 0.f, 0.f, 0.f};

    float4 regs[4];
    #pragma unroll
    for (int j = 0; j < 4; ++j)
        regs[j] = *reinterpret_cast<const float4*>(base + (size_t)(lr + 16 * j) * HWL + lc * 4);

    for (int tI = 0; tI < tiles; ++tI) {
        __syncthreads();
        #pragma unroll
        for (int j = 0; j < 4; ++j) {
            float4 v = regs[j];
            psum[j] += (v.x + v.y) + (v.z + v.w);
            float4 h, l;
            h.x = hi_tf32(v.x); h.y = hi_tf32(v.y); h.z = hi_tf32(v.z); h.w = hi_tf32(v.w);
            l.x = 2.f * (v.x - h.x); l.y = 2.f * (v.y - h.y);
            l.z = 2.f * (v.z - h.z); l.w = 2.f * (v.w - h.w);
            *reinterpret_cast<float4*>(Xhi + (lr + 16 * j) * RL + lc * 4) = h;
            *reinterpret_cast<float4*>(Xlo + (lr + 16 * j) * RL + lc * 4) = l;
        }
        __syncthreads();
        if (tI + 1 < tiles) {
            const float* b2 = base + (tI + 1) * 64;
            #pragma unroll
            for (int j = 0; j < 4; ++j)
                regs[j] = *reinterpret_cast<const float4*>(b2 + (size_t)(lr + 16 * j) * HWL + lc * 4);
        }

        #pragma unroll
        for (int ks = 0; ks < 8; ++ks) {
            const int ka = 8 * ks + c;
            uint32_t ah0 = fbits(Xhi[(mbase + r) * RL + ka]);
            uint32_t ah1 = fbits(Xhi[(mbase + r + 8) * RL + ka]);
            uint32_t ah2 = fbits(Xhi[(mbase + r) * RL + ka + 4]);
            uint32_t ah3 = fbits(Xhi[(mbase + r + 8) * RL + ka + 4]);
            #pragma unroll
            for (int u = 0; u < 4; ++u) {
                const int brow = (nt0 + u) * 8 + r;
                uint32_t bh0 = fbits(Xhi[brow * RL + ka]);
                uint32_t bh1 = fbits(Xhi[brow * RL + ka + 4]);
                uint32_t bl0 = fbits(Xlo[brow * RL + ka]);
                uint32_t bl1 = fbits(Xlo[brow * RL + ka + 4]);
                mma_tf32(acc[u], ah0, ah1, ah2, ah3, bh0, bh1);
                mma_tf32(acc[u], ah0, ah1, ah2, ah3, bl0, bl1);
            }
        }
    }

    __syncthreads();
    #pragma unroll
    for (int j = 0; j < 4; ++j) Xhi[(lr + 16 * j) * 16 + lc] = psum[j];
    __syncthreads();
    const int p = n * 4 + q;
    if (tid < 64) {
        float s = 0.f;
        #pragma unroll
        for (int k = 0; k < 16; ++k) s += Xhi[tid * 16 + k];
        g_psum[g][p][tid] = s;
    }
    float* outp = &g_pcov[g][p][0];
    #pragma unroll
    for (int u = 0; u < 4; ++u) {
        int col = (nt0 + u) * 8 + 2 * c;
        *reinterpret_cast<float2*>(outp + (size_t)(mbase + r) * 64 + col)     = make_float2(acc[u][0], acc[u][1]);
        *reinterpret_cast<float2*>(outp + (size_t)(mbase + r + 8) * 64 + col) = make_float2(acc[u][2], acc[u][3]);
    }
}

// =============================================================================
// Kernel 2a: reduce channel sums -> mu.  grid 8, 64 threads.
// =============================================================================
__global__ __launch_bounds__(64) void k_mean() {
    const int g = blockIdx.x, i = threadIdx.x;
    float s = 0.f;
    #pragma unroll 4
    for (int p = 0; p < NPART; ++p) s += g_psum[g][p][i];
    g_mu[g * LL + i] = s / (float)MTOT;
}

// =============================================================================
// Kernel 2b: reduce + symmetrize: cov_ij = (F_ij + F_ji)/2 / M - mu_i mu_j.
// =============================================================================
__global__ __launch_bounds__(256) void k_cov_finalize() {
    const int g = blockIdx.y;
    const int e = blockIdx.x * 256 + threadIdx.x;
    const int i = e >> 6, j = e & 63;
    const int et = j * 64 + i;
    float s0 = 0.f, s1 = 0.f, s2 = 0.f, s3 = 0.f;
    float t0 = 0.f, t1 = 0.f, t2 = 0.f, t3 = 0.f;
    #pragma unroll 4
    for (int p = 0; p < NPART; p += 4) {
        s0 += g_pcov[g][p + 0][e];
        s1 += g_pcov[g][p + 1][e];
        s2 += g_pcov[g][p + 2][e];
        s3 += g_pcov[g][p + 3][e];
        t0 += g_pcov[g][p + 0][et];
        t1 += g_pcov[g][p + 1][et];
        t2 += g_pcov[g][p + 2][et];
        t3 += g_pcov[g][p + 3][et];
    }
    float F  = ((s0 + s1) + (s2 + s3));
    float Ft = ((t0 + t1) + (t2 + t3));
    float c = (F + Ft) * 0.5f / (float)MTOT - g_mu[g * LL + i] * g_mu[g * LL + j];
    if (i == j) c += EPSV;
    g_cov[g * LL * LL + e] = c;
}

// =============================================================================
// Kernel 3: power iteration + deflation. Normalization deferred: renorm every
// 4th iteration (range guard; spectrum in [eps, ~2.5] keeps fp32 safe) + exact
// final normalization. Direction identical to reference up to fp rounding.
// =============================================================================
#define MATVEC64(res, Aarr, vptr) {                                        \
    float y0 = 0.f, y1 = 0.f, y2 = 0.f, y3 = 0.f;                          \
    _Pragma("unroll")                                                      \
    for (int j_ = 0; j_ < 64; j_ += 4) {                                   \
        y0 = fmaf(Aarr[j_ + 0], (vptr)[j_ + 0], y0);                       \
        y1 = fmaf(Aarr[j_ + 1], (vptr)[j_ + 1], y1);                       \
        y2 = fmaf(Aarr[j_ + 2], (vptr)[j_ + 2], y2);                       \
        y3 = fmaf(Aarr[j_ + 3], (vptr)[j_ + 3], y3);                       \
    }                                                                      \
    res = (y0 + y1) + (y2 + y3);                                           \
}

__device__ __forceinline__ float sumsq64(const float* v) {
    float y0 = 0.f, y1 = 0.f, y2 = 0.f, y3 = 0.f;
    #pragma unroll
    for (int j = 0; j < 64; j += 4) {
        y0 = fmaf(v[j + 0], v[j + 0], y0);
        y1 = fmaf(v[j + 1], v[j + 1], y1);
        y2 = fmaf(v[j + 2], v[j + 2], y2);
        y3 = fmaf(v[j + 3], v[j + 3], y3);
    }
    return (y0 + y1) + (y2 + y3);
}
__device__ __forceinline__ float dot64(const float* a, const float* b) {
    float y0 = 0.f, y1 = 0.f, y2 = 0.f, y3 = 0.f;
    #pragma unroll
    for (int j = 0; j < 64; j += 4) {
        y0 = fmaf(a[j + 0], b[j + 0], y0);
        y1 = fmaf(a[j + 1], b[j + 1], y1);
        y2 = fmaf(a[j + 2], b[j + 2], y2);
        y3 = fmaf(a[j + 3], b[j + 3], y3);
    }
    return (y0 + y1) + (y2 + y3);
}

__global__ __launch_bounds__(64) void k_pi(const float* __restrict__ vinit) {
    const int g = blockIdx.x, i = threadIdx.x;
    __shared__ float vs[2][64];
    __shared__ float av[64];

    float A[64], S[64];
    #pragma unroll
    for (int j = 0; j < 64; ++j) {
        A[j] = g_cov[g * LL * LL + i * 64 + j];
        S[j] = 0.f;
    }

    float lam_prev = 0.f;

    for (int e = 0; e < 64; ++e) {
        __syncthreads();
        vs[0][i] = vinit[((size_t)g * LL + e) * LL + i];   // raw v0 (scale-free)
        __syncthreads();

        int cur = 0;
        #pragma unroll 1
        for (int it = 0; it < 19; ++it) {
            float y;
            MATVEC64(y, A, vs[cur]);
            vs[cur ^ 1][i] = y;
            __syncthreads();
            if ((it & 3) == 3) {
                // periodic range-guard renorm; scaled vector goes back to vs[cur]
                float n2  = sumsq64(vs[cur ^ 1]);
                float inv = rsqrtf(n2);
                vs[cur][i] = y * inv;
                __syncthreads();
                // cur unchanged: scaled vector is in vs[cur]
            } else {
                cur ^= 1;
            }
        }

        // final exact normalization
        float n2  = sumsq64(vs[cur]);
        float inv = 1.f / (sqrtf(n2) + 1e-12f);
        float vi  = vs[cur][i] * inv;
        __syncthreads();
        vs[cur ^ 1][i] = vi;
        __syncthreads();
        cur ^= 1;

        float Avi;
        MATVEC64(Avi, A, vs[cur]);
        av[i] = Avi;
        __syncthreads();

        float vAv = dot64(vs[cur], av);
        float vv  = sumsq64(vs[cur]);
        float lam = vAv / vv;

        if (e > 0 && (lam_prev < lam || lam < EPSV)) break;

        float svi = rsqrtf(lam) * vi;
        #pragma unroll
        for (int j = 0; j < 64; ++j) {
            float vj = vs[cur][j];
            S[j] = fmaf(svi, vj, S[j]);
            A[j] = fmaf(-Avi, vj, A[j]);
        }
        lam_prev = lam;
    }

    #pragma unroll
    for (int j = 0; j < 64; ++j) g_subT[g * LL * LL + j * 64 + i] = S[j];

    float t = 0.f;
    #pragma unroll
    for (int j = 0; j < 64; ++j) t = fmaf(S[j], g_mu[g * LL + j], t);
    g_t[g * LL + i] = t;
}

// =============================================================================
// Kernel 4: apply whitening + affine via 3xTF32 MMA.
// S fragments in registers (R14); X tile stored as interleaved (hi,lo) pairs,
// row stride PRX=136 -> each B fragment operand pair is ONE LDS.64
// (bank-verified conflict-free: addr mod 32 = 8c + 2r + const per phase).
// grid (7 hw-chunks, 32 n, 8 g), 128 threads.
// =============================================================================
#define AP_SMEM_BYTES (64 * PRX * 4)

__global__ __launch_bounds__(128) void k_apply(const float* __restrict__ x,
                                               const float* __restrict__ wgt,
                                               const float* __restrict__ bia,
                                               float* __restrict__ out) {
    extern __shared__ __align__(16) float Xp[];   // [k][n] (hi,lo) pairs

    const int hb = blockIdx.x;            // 0..6 (448 hw each)
    const int n  = blockIdx.y;
    const int g  = blockIdx.z;
    const int tid = threadIdx.x, wid = tid >> 5, lane = tid & 31;
    const int r = lane >> 2, c = lane & 3;
    const int mbase = wid * 16;
    const int lr = tid >> 4, lc = tid & 15;

    const float* xbase = x   + ((size_t)n * CC + (size_t)g * LL) * HWL + hb * 448;
    float*       obase = out + ((size_t)n * CC + (size_t)g * LL) * HWL + hb * 448;

    float4 regs[8];
    #pragma unroll
    for (int j = 0; j < 8; ++j)
        regs[j] = *reinterpret_cast<const float4*>(xbase + (size_t)(lr + 8 * j) * HWL + lc * 4);

    // S fragments -> registers; split hi/lo once
    float ah[8][4], al[8][4];
    {
        const float* Sg = g_subT + g * 4096;
        #pragma unroll
        for (int ks = 0; ks < 8; ++ks) {
            const int ka = 8 * ks + c;
            float s0 = Sg[ka * 64 + mbase + r];
            float s1 = Sg[ka * 64 + mbase + r + 8];
            float s2 = Sg[(ka + 4) * 64 + mbase + r];
            float s3 = Sg[(ka + 4) * 64 + mbase + r + 8];
            ah[ks][0] = hi_tf32(s0); al[ks][0] = s0 - ah[ks][0];
            ah[ks][1] = hi_tf32(s1); al[ks][1] = s1 - ah[ks][1];
            ah[ks][2] = hi_tf32(s2); al[ks][2] = s2 - ah[ks][2];
            ah[ks][3] = hi_tf32(s3); al[ks][3] = s3 - ah[ks][3];
        }
    }

    const int gc0 = g * LL + mbase + r, gc1 = gc0 + 8;
    const float w0 = wgt[gc0], w1 = wgt[gc1];
    const float q0 = bia[gc0] - g_t[gc0] * w0;
    const float q1 = bia[gc1] - g_t[gc1] * w1;

    for (int t = 0; t < 7; ++t) {
        __syncthreads();
        #pragma unroll
        for (int j = 0; j < 8; ++j) {
            float4 v = regs[j];
            float hx = hi_tf32(v.x), hy = hi_tf32(v.y), hz = hi_tf32(v.z), hw = hi_tf32(v.w);
            float* dst = Xp + (lr + 8 * j) * PRX + lc * 8;
            *reinterpret_cast<float4*>(dst)     = make_float4(hx, v.x - hx, hy, v.y - hy);
            *reinterpret_cast<float4*>(dst + 4) = make_float4(hz, v.z - hz, hw, v.w - hw);
        }
        __syncthreads();
        if (t < 6) {
            const float* b2 = xbase + (t + 1) * 64;
            #pragma unroll
            for (int j = 0; j < 8; ++j)
                regs[j] = *reinterpret_cast<const float4*>(b2 + (size_t)(lr + 8 * j) * HWL + lc * 4);
        }

        float acc[8][4];
        #pragma unroll
        for (int nt = 0; nt < 8; ++nt)
            #pragma unroll
            for (int j = 0; j < 4; ++j) acc[nt][j] = 0.f;

        #pragma unroll
        for (int ks = 0; ks < 8; ++ks) {
            const int ka = 8 * ks + c;
            uint32_t A0 = fbits(ah[ks][0]), A1 = fbits(ah[ks][1]);
            uint32_t A2 = fbits(ah[ks][2]), A3 = fbits(ah[ks][3]);
            uint32_t L0 = fbits(al[ks][0]), L1 = fbits(al[ks][1]);
            uint32_t L2 = fbits(al[ks][2]), L3 = fbits(al[ks][3]);
            #pragma unroll
            for (int nt = 0; nt < 8; ++nt) {
                const int bn = nt * 8 + r;
                float2 p0 = *reinterpret_cast<const float2*>(Xp + ka * PRX + 2 * bn);         // (bh0, bl0)
                float2 p1 = *reinterpret_cast<const float2*>(Xp + (ka + 4) * PRX + 2 * bn);   // (bh1, bl1)
                uint32_t bh0 = fbits(p0.x), bl0 = fbits(p0.y);
                uint32_t bh1 = fbits(p1.x), bl1 = fbits(p1.y);
                mma_tf32(acc[nt], A0, A1, A2, A3, bh0, bh1);
                mma_tf32(acc[nt], A0, A1, A2, A3, bl0, bl1);
                mma_tf32(acc[nt], L0, L1, L2, L3, bh0, bh1);
            }
        }

        float* op = obase + t * 64;
        #pragma unroll
        for (int nt = 0; nt < 8; ++nt) {
            int col = nt * 8 + 2 * c;
            float2 v0 = make_float2(fmaf(acc[nt][0], w0, q0), fmaf(acc[nt][1], w0, q0));
            float2 v1 = make_float2(fmaf(acc[nt][2], w1, q1), fmaf(acc[nt][3], w1, q1));
            *reinterpret_cast<float2*>(op + (size_t)(mbase + r) * HWL + col)     = v0;
            *reinterpret_cast<float2*>(op + (size_t)(mbase + r + 8) * HWL + col) = v1;
        }
    }
}

// =============================================================================
extern "C" void kernel_launch(void* const* d_in, const int* in_sizes, int n_in,
                              void* d_out, int out_size) {
    const float* x     = (const float*)d_in[0];
    const float* vinit = (const float*)d_in[1];
    const float* wgt   = (const float*)d_in[2];
    const float* bia   = (const float*)d_in[3];
    float* out = (float*)d_out;
    (void)in_sizes; (void)n_in; (void)out_size;

    cudaFuncSetAttribute(k_apply, cudaFuncAttributeMaxDynamicSharedMemorySize, AP_SMEM_BYTES);

    k_cov_partial<<<dim3(4, 32, 8), 256>>>(x);
    k_mean<<<8, 64>>>();
    k_cov_finalize<<<dim3(16, 8), 256>>>();
    k_pi<<<8, 64>>>(vinit);
    k_apply<<<dim3(7, 32, 8), 128, AP_SMEM_BYTES>>>(x, wgt, bia, out);
}

// round 17
// speedup vs baseline: 1.0465x; 1.0465x over previous
#include <cuda_runtime.h>
#include <cstdint>

// Problem constants
#define NN   32
#define CC   512
#define HWL  3136        // 56*56
#define GG   8
#define LL   64
#define MTOT 100352      // NN*HWL
#define EPSV 1e-4f
#define NPART 128        // 32 n-chunks * 4 k-chunks
#define RL   68          // smem row stride (floats) for cov's [ch][k]
#define RLX  72          // smem row stride for apply's X [k][n]

// ---------------- scratch (device globals; no allocation allowed) -------------
__device__ float g_pcov[GG][NPART][LL * LL];  // partial F = HH^T + H(2L)^T
__device__ float g_psum[GG][NPART][LL];       // partial channel sums
__device__ float g_mu[CC];
__device__ float g_cov[GG * LL * LL];
__device__ float g_subT[GG * LL * LL];        // whitening subspace, TRANSPOSED [g][k][i] = S[i][k]
__device__ float g_t[CC];                     // t[c] = sum_j S[c][j] * mu[g*64+j]

// ---------------- helpers ------------------------------------------------------
__device__ __forceinline__ void mma_tf32(float c[4],
                                         uint32_t a0, uint32_t a1, uint32_t a2, uint32_t a3,
                                         uint32_t b0, uint32_t b1) {
    asm volatile(
        "mma.sync.aligned.m16n8k8.row.col.f32.tf32.tf32.f32 "
        "{%0,%1,%2,%3}, {%4,%5,%6,%7}, {%8,%9}, {%0,%1,%2,%3};"
        : "+f"(c[0]), "+f"(c[1]), "+f"(c[2]), "+f"(c[3])
        : "r"(a0), "r"(a1), "r"(a2), "r"(a3), "r"(b0), "r"(b1));
}
__device__ __forceinline__ float hi_tf32(float x) {
    return __uint_as_float(__float_as_uint(x) & 0xFFFFE000u);
}
__device__ __forceinline__ uint32_t fbits(float x) { return __float_as_uint(x); }

// =============================================================================
// Kernel 1: partial F = H H^T + H (2L)^T via tf32 MMA (R15 verbatim).
// grid (4 k-chunks, 32 n, 8 g), 256 threads (8 warps).
// =============================================================================
__global__ __launch_bounds__(256) void k_cov_partial(const float* __restrict__ x) {
    const int q = blockIdx.x;           // k-chunk 0..3
    const int n = blockIdx.y;
    const int g = blockIdx.z;
    __shared__ __align__(16) float Xhi[64 * RL];
    __shared__ __align__(16) float Xlo[64 * RL];   // holds 2*lo

    const int tid = threadIdx.x, wid = tid >> 5, lane = tid & 31;
    const int r = lane >> 2, c = lane & 3;
    const int mbase = (wid & 3) * 16;
    const int nt0   = (wid >> 2) * 4;
    const int lr = tid >> 4, lc = tid & 15;

    const int tiles = (q == 0) ? 13 : 12;
    const int k0    = (q == 0) ? 0 : (832 + (q - 1) * 768);
    const float* base = x + ((size_t)n * CC + (size_t)g * LL) * HWL + k0;

    float acc[4][4];
    #pragma unroll
    for (int t = 0; t < 4; ++t)
        #pragma unroll
        for (int j = 0; j < 4; ++j) acc[t][j] = 0.f;
    float psum[4] = {0.f, 0.f, 0.f, 0.f};

    float4 regs[4];
    #pragma unroll
    for (int j = 0; j < 4; ++j)
        regs[j] = *reinterpret_cast<const float4*>(base + (size_t)(lr + 16 * j) * HWL + lc * 4);

    for (int tI = 0; tI < tiles; ++tI) {
        __syncthreads();
        #pragma unroll
        for (int j = 0; j < 4; ++j) {
            float4 v = regs[j];
            psum[j] += (v.x + v.y) + (v.z + v.w);
            float4 h, l;
            h.x = hi_tf32(v.x); h.y = hi_tf32(v.y); h.z = hi_tf32(v.z); h.w = hi_tf32(v.w);
            l.x = 2.f * (v.x - h.x); l.y = 2.f * (v.y - h.y);
            l.z = 2.f * (v.z - h.z); l.w = 2.f * (v.w - h.w);
            *reinterpret_cast<float4*>(Xhi + (lr + 16 * j) * RL + lc * 4) = h;
            *reinterpret_cast<float4*>(Xlo + (lr + 16 * j) * RL + lc * 4) = l;
        }
        __syncthreads();
        if (tI + 1 < tiles) {
            const float* b2 = base + (tI + 1) * 64;
            #pragma unroll
            for (int j = 0; j < 4; ++j)
                regs[j] = *reinterpret_cast<const float4*>(b2 + (size_t)(lr + 16 * j) * HWL + lc * 4);
        }

        #pragma unroll
        for (int ks = 0; ks < 8; ++ks) {
            const int ka = 8 * ks + c;
            uint32_t ah0 = fbits(Xhi[(mbase + r) * RL + ka]);
            uint32_t ah1 = fbits(Xhi[(mbase + r + 8) * RL + ka]);
            uint32_t ah2 = fbits(Xhi[(mbase + r) * RL + ka + 4]);
            uint32_t ah3 = fbits(Xhi[(mbase + r + 8) * RL + ka + 4]);
            #pragma unroll
            for (int u = 0; u < 4; ++u) {
                const int brow = (nt0 + u) * 8 + r;
                uint32_t bh0 = fbits(Xhi[brow * RL + ka]);
                uint32_t bh1 = fbits(Xhi[brow * RL + ka + 4]);
                uint32_t bl0 = fbits(Xlo[brow * RL + ka]);
                uint32_t bl1 = fbits(Xlo[brow * RL + ka + 4]);
                mma_tf32(acc[u], ah0, ah1, ah2, ah3, bh0, bh1);
                mma_tf32(acc[u], ah0, ah1, ah2, ah3, bl0, bl1);
            }
        }
    }

    __syncthreads();
    #pragma unroll
    for (int j = 0; j < 4; ++j) Xhi[(lr + 16 * j) * 16 + lc] = psum[j];
    __syncthreads();
    const int p = n * 4 + q;
    if (tid < 64) {
        float s = 0.f;
        #pragma unroll
        for (int k = 0; k < 16; ++k) s += Xhi[tid * 16 + k];
        g_psum[g][p][tid] = s;
    }
    float* outp = &g_pcov[g][p][0];
    #pragma unroll
    for (int u = 0; u < 4; ++u) {
        int col = (nt0 + u) * 8 + 2 * c;
        *reinterpret_cast<float2*>(outp + (size_t)(mbase + r) * 64 + col)     = make_float2(acc[u][0], acc[u][1]);
        *reinterpret_cast<float2*>(outp + (size_t)(mbase + r + 8) * 64 + col) = make_float2(acc[u][2], acc[u][3]);
    }
}

// =============================================================================
// Kernel 2a: reduce channel sums -> mu.  grid 8, 64 threads.
// =============================================================================
__global__ __launch_bounds__(64) void k_mean() {
    const int g = blockIdx.x, i = threadIdx.x;
    float s = 0.f;
    #pragma unroll 4
    for (int p = 0; p < NPART; ++p) s += g_psum[g][p][i];
    g_mu[g * LL + i] = s / (float)MTOT;
}

// =============================================================================
// Kernel 2b: reduce + symmetrize: cov_ij = (F_ij + F_ji)/2 / M - mu_i mu_j.
// =============================================================================
__global__ __launch_bounds__(256) void k_cov_finalize() {
    const int g = blockIdx.y;
    const int e = blockIdx.x * 256 + threadIdx.x;
    const int i = e >> 6, j = e & 63;
    const int et = j * 64 + i;
    float s0 = 0.f, s1 = 0.f, s2 = 0.f, s3 = 0.f;
    float t0 = 0.f, t1 = 0.f, t2 = 0.f, t3 = 0.f;
    #pragma unroll 4
    for (int p = 0; p < NPART; p += 4) {
        s0 += g_pcov[g][p + 0][e];
        s1 += g_pcov[g][p + 1][e];
        s2 += g_pcov[g][p + 2][e];
        s3 += g_pcov[g][p + 3][e];
        t0 += g_pcov[g][p + 0][et];
        t1 += g_pcov[g][p + 1][et];
        t2 += g_pcov[g][p + 2][et];
        t3 += g_pcov[g][p + 3][et];
    }
    float F  = ((s0 + s1) + (s2 + s3));
    float Ft = ((t0 + t1) + (t2 + t3));
    float c = (F + Ft) * 0.5f / (float)MTOT - g_mu[g * LL + i] * g_mu[g * LL + j];
    if (i == j) c += EPSV;
    g_cov[g * LL * LL + e] = c;
}

// =============================================================================
// Kernel 3: power iteration + deflation, deferred normalization (R16 — proven).
// =============================================================================
#define MATVEC64(res, Aarr, vptr) {                                        \
    float y0 = 0.f, y1 = 0.f, y2 = 0.f, y3 = 0.f;                          \
    _Pragma("unroll")                                                      \
    for (int j_ = 0; j_ < 64; j_ += 4) {                                   \
        y0 = fmaf(Aarr[j_ + 0], (vptr)[j_ + 0], y0);                       \
        y1 = fmaf(Aarr[j_ + 1], (vptr)[j_ + 1], y1);                       \
        y2 = fmaf(Aarr[j_ + 2], (vptr)[j_ + 2], y2);                       \
        y3 = fmaf(Aarr[j_ + 3], (vptr)[j_ + 3], y3);                       \
    }                                                                      \
    res = (y0 + y1) + (y2 + y3);                                           \
}

__device__ __forceinline__ float sumsq64(const float* v) {
    float y0 = 0.f, y1 = 0.f, y2 = 0.f, y3 = 0.f;
    #pragma unroll
    for (int j = 0; j < 64; j += 4) {
        y0 = fmaf(v[j + 0], v[j + 0], y0);
        y1 = fmaf(v[j + 1], v[j + 1], y1);
        y2 = fmaf(v[j + 2], v[j + 2], y2);
        y3 = fmaf(v[j + 3], v[j + 3], y3);
    }
    return (y0 + y1) + (y2 + y3);
}
__device__ __forceinline__ float dot64(const float* a, const float* b) {
    float y0 = 0.f, y1 = 0.f, y2 = 0.f, y3 = 0.f;
    #pragma unroll
    for (int j = 0; j < 64; j += 4) {
        y0 = fmaf(a[j + 0], b[j + 0], y0);
        y1 = fmaf(a[j + 1], b[j + 1], y1);
        y2 = fmaf(a[j + 2], b[j + 2], y2);
        y3 = fmaf(a[j + 3], b[j + 3], y3);
    }
    return (y0 + y1) + (y2 + y3);
}

__global__ __launch_bounds__(64) void k_pi(const float* __restrict__ vinit) {
    const int g = blockIdx.x, i = threadIdx.x;
    __shared__ float vs[2][64];
    __shared__ float av[64];

    float A[64], S[64];
    #pragma unroll
    for (int j = 0; j < 64; ++j) {
        A[j] = g_cov[g * LL * LL + i * 64 + j];
        S[j] = 0.f;
    }

    float lam_prev = 0.f;

    for (int e = 0; e < 64; ++e) {
        __syncthreads();
        vs[0][i] = vinit[((size_t)g * LL + e) * LL + i];   // raw v0 (scale-free)
        __syncthreads();

        int cur = 0;
        #pragma unroll 1
        for (int it = 0; it < 19; ++it) {
            float y;
            MATVEC64(y, A, vs[cur]);
            vs[cur ^ 1][i] = y;
            __syncthreads();
            if ((it & 3) == 3) {
                float n2  = sumsq64(vs[cur ^ 1]);
                float inv = rsqrtf(n2);
                vs[cur][i] = y * inv;
                __syncthreads();
            } else {
                cur ^= 1;
            }
        }

        float n2  = sumsq64(vs[cur]);
        float inv = 1.f / (sqrtf(n2) + 1e-12f);
        float vi  = vs[cur][i] * inv;
        __syncthreads();
        vs[cur ^ 1][i] = vi;
        __syncthreads();
        cur ^= 1;

        float Avi;
        MATVEC64(Avi, A, vs[cur]);
        av[i] = Avi;
        __syncthreads();

        float vAv = dot64(vs[cur], av);
        float vv  = sumsq64(vs[cur]);
        float lam = vAv / vv;

        if (e > 0 && (lam_prev < lam || lam < EPSV)) break;

        float svi = rsqrtf(lam) * vi;
        #pragma unroll
        for (int j = 0; j < 64; ++j) {
            float vj = vs[cur][j];
            S[j] = fmaf(svi, vj, S[j]);
            A[j] = fmaf(-Avi, vj, A[j]);
        }
        lam_prev = lam;
    }

    #pragma unroll
    for (int j = 0; j < 64; ++j) g_subT[g * LL * LL + j * 64 + i] = S[j];

    float t = 0.f;
    #pragma unroll
    for (int j = 0; j < 64; ++j) t = fmaf(S[j], g_mu[g * LL + j], t);
    g_t[g * LL + i] = t;
}

// =============================================================================
// Kernel 4: apply whitening + affine via 3xTF32 MMA, S fragments in registers,
// split Xh/Xl arrays at stride RLX=72 (R15 verbatim — proven fastest).
// grid (7 hw-chunks, 32 n, 8 g), 128 threads.
// =============================================================================
#define AP_SMEM_BYTES (2 * 64 * RLX * 4)

__global__ __launch_bounds__(128) void k_apply(const float* __restrict__ x,
                                               const float* __restrict__ wgt,
                                               const float* __restrict__ bia,
                                               float* __restrict__ out) {
    extern __shared__ __align__(16) float smem[];
    float* Xh = smem;
    float* Xl = smem + 64 * RLX;

    const int hb = blockIdx.x;            // 0..6 (448 hw each)
    const int n  = blockIdx.y;
    const int g  = blockIdx.z;
    const int tid = threadIdx.x, wid = tid >> 5, lane = tid & 31;
    const int r = lane >> 2, c = lane & 3;
    const int mbase = wid * 16;
    const int lr = tid >> 4, lc = tid & 15;

    const float* xbase = x   + ((size_t)n * CC + (size_t)g * LL) * HWL + hb * 448;
    float*       obase = out + ((size_t)n * CC + (size_t)g * LL) * HWL + hb * 448;

    float4 regs[8];
    #pragma unroll
    for (int j = 0; j < 8; ++j)
        regs[j] = *reinterpret_cast<const float4*>(xbase + (size_t)(lr + 8 * j) * HWL + lc * 4);

    // S fragments -> registers; split hi/lo once
    float ah[8][4], al[8][4];
    {
        const float* Sg = g_subT + g * 4096;
        #pragma unroll
        for (int ks = 0; ks < 8; ++ks) {
            const int ka = 8 * ks + c;
            float s0 = Sg[ka * 64 + mbase + r];
            float s1 = Sg[ka * 64 + mbase + r + 8];
            float s2 = Sg[(ka + 4) * 64 + mbase + r];
            float s3 = Sg[(ka + 4) * 64 + mbase + r + 8];
            ah[ks][0] = hi_tf32(s0); al[ks][0] = s0 - ah[ks][0];
            ah[ks][1] = hi_tf32(s1); al[ks][1] = s1 - ah[ks][1];
            ah[ks][2] = hi_tf32(s2); al[ks][2] = s2 - ah[ks][2];
            ah[ks][3] = hi_tf32(s3); al[ks][3] = s3 - ah[ks][3];
        }
    }

    const int gc0 = g * LL + mbase + r, gc1 = gc0 + 8;
    const float w0 = wgt[gc0], w1 = wgt[gc1];
    const float q0 = bia[gc0] - g_t[gc0] * w0;
    const float q1 = bia[gc1] - g_t[gc1] * w1;

    for (int t = 0; t < 7; ++t) {
        __syncthreads();
        #pragma unroll
        for (int j = 0; j < 8; ++j) {
            float4 v = regs[j];
            float4 h, l;
            h.x = hi_tf32(v.x); h.y = hi_tf32(v.y); h.z = hi_tf32(v.z); h.w = hi_tf32(v.w);
            l.x = v.x - h.x; l.y = v.y - h.y; l.z = v.z - h.z; l.w = v.w - h.w;
            *reinterpret_cast<float4*>(Xh + (lr + 8 * j) * RLX + lc * 4) = h;
            *reinterpret_cast<float4*>(Xl + (lr + 8 * j) * RLX + lc * 4) = l;
        }
        __syncthreads();
        if (t < 6) {
            const float* b2 = xbase + (t + 1) * 64;
            #pragma unroll
            for (int j = 0; j < 8; ++j)
                regs[j] = *reinterpret_cast<const float4*>(b2 + (size_t)(lr + 8 * j) * HWL + lc * 4);
        }

        float acc[8][4];
        #pragma unroll
        for (int nt = 0; nt < 8; ++nt)
            #pragma unroll
            for (int j = 0; j < 4; ++j) acc[nt][j] = 0.f;

        #pragma unroll
        for (int ks = 0; ks < 8; ++ks) {
            const int ka = 8 * ks + c;
            uint32_t A0 = fbits(ah[ks][0]), A1 = fbits(ah[ks][1]);
            uint32_t A2 = fbits(ah[ks][2]), A3 = fbits(ah[ks][3]);
            uint32_t L0 = fbits(al[ks][0]), L1 = fbits(al[ks][1]);
            uint32_t L2 = fbits(al[ks][2]), L3 = fbits(al[ks][3]);
            #pragma unroll
            for (int nt = 0; nt < 8; ++nt) {
                const int bn = nt * 8 + r;
                uint32_t bh0 = fbits(Xh[ka * RLX + bn]);
                uint32_t bh1 = fbits(Xh[(ka + 4) * RLX + bn]);
                uint32_t bl0 = fbits(Xl[ka * RLX + bn]);
                uint32_t bl1 = fbits(Xl[(ka + 4) * RLX + bn]);
                mma_tf32(acc[nt], A0, A1, A2, A3, bh0, bh1);
                mma_tf32(acc[nt], A0, A1, A2, A3, bl0, bl1);
                mma_tf32(acc[nt], L0, L1, L2, L3, bh0, bh1);
            }
        }

        float* op = obase + t * 64;
        #pragma unroll
        for (int nt = 0; nt < 8; ++nt) {
            int col = nt * 8 + 2 * c;
            float2 v0 = make_float2(fmaf(acc[nt][0], w0, q0), fmaf(acc[nt][1], w0, q0));
            float2 v1 = make_float2(fmaf(acc[nt][2], w1, q1), fmaf(acc[nt][3], w1, q1));
            *reinterpret_cast<float2*>(op + (size_t)(mbase + r) * HWL + col)     = v0;
            *reinterpret_cast<float2*>(op + (size_t)(mbase + r + 8) * HWL + col) = v1;
        }
    }
}

// =============================================================================
extern "C" void kernel_launch(void* const* d_in, const int* in_sizes, int n_in,
                              void* d_out, int out_size) {
    const float* x     = (const float*)d_in[0];
    const float* vinit = (const float*)d_in[1];
    const float* wgt   = (const float*)d_in[2];
    const float* bia   = (const float*)d_in[3];
    float* out = (float*)d_out;
    (void)in_sizes; (void)n_in; (void)out_size;

    cudaFuncSetAttribute(k_apply, cudaFuncAttributeMaxDynamicSharedMemorySize, AP_SMEM_BYTES);

    k_cov_partial<<<dim3(4, 32, 8), 256>>>(x);
    k_mean<<<8, 64>>>();
    k_cov_finalize<<<dim3(16, 8), 256>>>();
    k_pi<<<8, 64>>>(vinit);
    k_apply<<<dim3(7, 32, 8), 128, AP_SMEM_BYTES>>>(x, wgt, bia, out);
}